// round 4
// baseline (speedup 1.0000x reference)
#include <cuda_runtime.h>

// ---------------- problem constants ----------------
#define N_NODES 16384
#define N_EDGES 524288
#define BATCH   32
#define DIM     64
#define OUTD    64
#define FEAT    (BATCH * DIM)   /* 2048 */
#define NMAT    5
#define WROWS   (DIM * NMAT)    /* 320 */
#define CHUNK   512             /* feature chunk (floats) for L2 residency */

// ---------------- device scratch (static: no allocations allowed) ----------
__device__ __align__(16) float g_x[NMAT][(size_t)N_NODES * FEAT];  // ~671 MB
__device__ float g_inv_drow[N_NODES];
__device__ float g_inv_dcol[N_NODES];
__device__ int   g_cnt1[N_NODES];
__device__ int   g_cnt2[N_NODES];
__device__ int   g_rowptr1[N_NODES + 1];
__device__ int   g_rowptr2[N_NODES + 1];
__device__ int   g_pos1[N_NODES];
__device__ int   g_pos2[N_NODES];
__device__ int   g_adj_col[2][N_EDGES];
__device__ float g_adj_val[2][N_EDGES];

// ---------------- f32x2 packed-FMA helpers (sm_10x) ----------------
#define FMA_F32X2(d, a, b, c) \
    asm("fma.rn.f32x2 %0, %1, %2, %3;" \
        : "=l"(d) : "l"(a), "l"(b), "l"(c))
#define PACK_DUP_F32X2(out, x) \
    asm("mov.b64 %0, {%1, %1};" : "=l"(out) : "f"(x))
#define PACK_F32X2(out, lo, hi) \
    asm("mov.b64 %0, {%1, %2};" : "=l"(out) : "f"(lo), "f"(hi))

// ---------------- build kernels ----------------
__global__ void k_init() {
    int i = blockIdx.x * blockDim.x + threadIdx.x;
    if (i < N_NODES) {
        g_inv_drow[i] = 0.f;
        g_inv_dcol[i] = 0.f;
        g_cnt1[i] = 0;
        g_cnt2[i] = 0;
    }
}

__global__ void k_degree(const float* __restrict__ adj,
                         const int* __restrict__ rows,
                         const int* __restrict__ cols) {
    int e = blockIdx.x * blockDim.x + threadIdx.x;
    if (e < N_EDGES) {
        int r = rows[e], c = cols[e];
        float a = adj[e];
        atomicAdd(&g_inv_drow[r], a);
        atomicAdd(&g_inv_dcol[c], a);
        atomicAdd(&g_cnt1[c], 1);   // support1 CSR keyed by dst = cols
        atomicAdd(&g_cnt2[r], 1);   // support2 CSR keyed by dst = rows
    }
}

// single-block: invert degrees + exclusive scan both histograms
__global__ void k_scan() {
    __shared__ int sh[1024];
    int t = threadIdx.x;

    for (int i = t; i < N_NODES; i += 1024) {
        float d = g_inv_drow[i]; g_inv_drow[i] = (d > 0.f) ? (1.f / d) : 0.f;
        float c = g_inv_dcol[i]; g_inv_dcol[i] = (c > 0.f) ? (1.f / c) : 0.f;
    }
    __syncthreads();

    {
        int base = t * 16;
        int local[16];
        int s = 0;
        #pragma unroll
        for (int i = 0; i < 16; i++) { local[i] = s; s += g_cnt1[base + i]; }
        sh[t] = s;
        __syncthreads();
        for (int off = 1; off < 1024; off <<= 1) {
            int v = (t >= off) ? sh[t - off] : 0;
            __syncthreads();
            sh[t] += v;
            __syncthreads();
        }
        int prev = t ? sh[t - 1] : 0;
        #pragma unroll
        for (int i = 0; i < 16; i++) {
            int p = prev + local[i];
            g_rowptr1[base + i] = p;
            g_pos1[base + i] = p;
        }
        if (t == 1023) g_rowptr1[N_NODES] = sh[1023];
        __syncthreads();
    }
    {
        int base = t * 16;
        int local[16];
        int s = 0;
        #pragma unroll
        for (int i = 0; i < 16; i++) { local[i] = s; s += g_cnt2[base + i]; }
        sh[t] = s;
        __syncthreads();
        for (int off = 1; off < 1024; off <<= 1) {
            int v = (t >= off) ? sh[t - off] : 0;
            __syncthreads();
            sh[t] += v;
            __syncthreads();
        }
        int prev = t ? sh[t - 1] : 0;
        #pragma unroll
        for (int i = 0; i < 16; i++) {
            int p = prev + local[i];
            g_rowptr2[base + i] = p;
            g_pos2[base + i] = p;
        }
        if (t == 1023) g_rowptr2[N_NODES] = sh[1023];
    }
}

__global__ void k_fill(const float* __restrict__ adj,
                       const int* __restrict__ rows,
                       const int* __restrict__ cols) {
    int e = blockIdx.x * blockDim.x + threadIdx.x;
    if (e < N_EDGES) {
        int r = rows[e], c = cols[e];
        float a = adj[e];
        int s1 = atomicAdd(&g_pos1[c], 1);
        g_adj_col[0][s1] = r;
        g_adj_val[0][s1] = a * g_inv_drow[r];
        int s2 = atomicAdd(&g_pos2[r], 1);
        g_adj_col[1][s2] = c;
        g_adj_val[1][s2] = a * g_inv_dcol[c];
    }
}

// chunked transpose: x0[n, b*64+d] = inputs[b, n, d] for f in [chunk*512, ...)
__global__ void k_transpose(const float* __restrict__ in, int chunk) {
    int idx = blockIdx.x * blockDim.x + threadIdx.x;   // over N*CHUNK/4
    int f4 = idx & 127;
    int n  = idx >> 7;
    int f  = (chunk << 9) + (f4 << 2);
    int b  = f >> 6;
    int d  = f & 63;
    float4 v = *reinterpret_cast<const float4*>(
        in + ((size_t)b * N_NODES * DIM + (size_t)n * DIM + d));
    *reinterpret_cast<float4*>(&g_x[0][(size_t)n * FEAT + f]) = v;
}

// ---------------- SpMM (CSR gather, one feature chunk, unroll-4) ----------
// out = (S @ xin)            if m_z < 0
// out = 2*(S @ xin) - xz     otherwise
// streamout: use evict-first stores (output not re-read until GEMM)
__global__ void __launch_bounds__(128)
k_spmm(int support, int m_in, int m_z, int m_out, int chunk, int streamout) {
    const int* __restrict__ rowptr = support ? g_rowptr2 : g_rowptr1;
    const int* __restrict__ colidx = g_adj_col[support];
    const float* __restrict__ val  = g_adj_val[support];
    const float* __restrict__ xin  = g_x[m_in];
    float* __restrict__ xout       = g_x[m_out];

    int n = blockIdx.x;
    int fbase = (chunk << 9) + (threadIdx.x << 2);

    int e   = rowptr[n];
    int end = rowptr[n + 1];

    float4 a0 = make_float4(0.f, 0.f, 0.f, 0.f);
    float4 a1 = make_float4(0.f, 0.f, 0.f, 0.f);
    float4 a2 = make_float4(0.f, 0.f, 0.f, 0.f);
    float4 a3 = make_float4(0.f, 0.f, 0.f, 0.f);

    for (; e + 4 <= end; e += 4) {
        int   c0 = colidx[e],     c1 = colidx[e + 1];
        int   c2 = colidx[e + 2], c3 = colidx[e + 3];
        float v0 = val[e],     v1 = val[e + 1];
        float v2 = val[e + 2], v3 = val[e + 3];
        float4 x0 = *reinterpret_cast<const float4*>(xin + (size_t)c0 * FEAT + fbase);
        float4 x1 = *reinterpret_cast<const float4*>(xin + (size_t)c1 * FEAT + fbase);
        float4 x2 = *reinterpret_cast<const float4*>(xin + (size_t)c2 * FEAT + fbase);
        float4 x3 = *reinterpret_cast<const float4*>(xin + (size_t)c3 * FEAT + fbase);
        a0.x += v0 * x0.x; a0.y += v0 * x0.y; a0.z += v0 * x0.z; a0.w += v0 * x0.w;
        a1.x += v1 * x1.x; a1.y += v1 * x1.y; a1.z += v1 * x1.z; a1.w += v1 * x1.w;
        a2.x += v2 * x2.x; a2.y += v2 * x2.y; a2.z += v2 * x2.z; a2.w += v2 * x2.w;
        a3.x += v3 * x3.x; a3.y += v3 * x3.y; a3.z += v3 * x3.z; a3.w += v3 * x3.w;
    }
    for (; e < end; e++) {
        int   c0 = colidx[e];
        float v0 = val[e];
        float4 x0 = *reinterpret_cast<const float4*>(xin + (size_t)c0 * FEAT + fbase);
        a0.x += v0 * x0.x; a0.y += v0 * x0.y; a0.z += v0 * x0.z; a0.w += v0 * x0.w;
    }
    a0.x += a1.x + a2.x + a3.x;
    a0.y += a1.y + a2.y + a3.y;
    a0.z += a1.z + a2.z + a3.z;
    a0.w += a1.w + a2.w + a3.w;

    size_t ooff = (size_t)n * FEAT + fbase;
    if (m_z >= 0) {
        // last use of the z slab before GEMM -> evict-first read
        float4 z = __ldcs(reinterpret_cast<const float4*>(g_x[m_z] + ooff));
        a0.x = 2.f * a0.x - z.x;
        a0.y = 2.f * a0.y - z.y;
        a0.z = 2.f * a0.z - z.z;
        a0.w = 2.f * a0.w - z.w;
    }
    if (streamout)
        __stcs(reinterpret_cast<float4*>(xout + ooff), a0);
    else
        *reinterpret_cast<float4*>(xout + ooff) = a0;
}

// ---------------- fused output GEMM (packed f32x2 FMA) ----------------
// out[b,n,:] = sum_{d,m} x_m[n, b*64+d] * W[d*5+m, :]
__global__ void __launch_bounds__(256, 2)
k_gemm(const float* __restrict__ W, const float* __restrict__ bias,
       float* __restrict__ out) {
    extern __shared__ float sw[];   // WROWS*OUTD floats (80 KB)
    __shared__ float sb[OUTD];

    for (int i = threadIdx.x; i < WROWS * OUTD; i += 256) sw[i] = W[i];
    if (threadIdx.x < OUTD) sb[threadIdx.x] = bias[threadIdx.x];
    __syncthreads();

    int row = blockIdx.x * 256 + threadIdx.x;  // row = b*N + n
    int b = row >> 14;        // / 16384
    int n = row & 16383;
    const int off = n * FEAT + b * DIM;

    unsigned long long acc[32];   // 32 packed f32x2 accumulators = 64 outputs
    #pragma unroll
    for (int k = 0; k < 32; k++) PACK_F32X2(acc[k], sb[2 * k], sb[2 * k + 1]);

    #pragma unroll 1
    for (int d4 = 0; d4 < 16; ++d4) {
        float4 xv[NMAT];
        #pragma unroll
        for (int m = 0; m < NMAT; m++)
            xv[m] = *reinterpret_cast<const float4*>(&g_x[m][(size_t)off + d4 * 4]);
        #pragma unroll
        for (int j = 0; j < 4; j++) {
            int d = d4 * 4 + j;
            #pragma unroll
            for (int m = 0; m < NMAT; m++) {
                float x = (j == 0) ? xv[m].x : (j == 1) ? xv[m].y
                        : (j == 2) ? xv[m].z : xv[m].w;
                unsigned long long xx;
                PACK_DUP_F32X2(xx, x);
                const ulonglong2* wrow =
                    reinterpret_cast<const ulonglong2*>(sw + (d * NMAT + m) * OUTD);
                #pragma unroll
                for (int o4 = 0; o4 < 16; o4++) {
                    ulonglong2 w = wrow[o4];   // 4 W floats (broadcast LDS.128)
                    FMA_F32X2(acc[2 * o4],     w.x, xx, acc[2 * o4]);
                    FMA_F32X2(acc[2 * o4 + 1], w.y, xx, acc[2 * o4 + 1]);
                }
            }
        }
    }

    ulonglong2* op = reinterpret_cast<ulonglong2*>(out + (size_t)row * OUTD);
    #pragma unroll
    for (int o4 = 0; o4 < 16; o4++)
        op[o4] = make_ulonglong2(acc[2 * o4], acc[2 * o4 + 1]);
}

// ---------------- launch ----------------
extern "C" void kernel_launch(void* const* d_in, const int* in_sizes, int n_in,
                              void* d_out, int out_size) {
    const float* inputs  = (const float*)d_in[0];
    const float* adj     = (const float*)d_in[1];
    const int*   rows    = (const int*)d_in[2];
    const int*   cols    = (const int*)d_in[3];
    const float* weights = (const float*)d_in[4];
    const float* biases  = (const float*)d_in[5];
    float*       out     = (float*)d_out;

    cudaFuncSetAttribute(k_gemm, cudaFuncAttributeMaxDynamicSharedMemorySize,
                         WROWS * OUTD * (int)sizeof(float));

    k_init<<<(N_NODES + 255) / 256, 256>>>();
    k_degree<<<N_EDGES / 256, 256>>>(adj, rows, cols);
    k_scan<<<1, 1024>>>();
    k_fill<<<N_EDGES / 256, 256>>>(adj, rows, cols);

    // Chunk-interleaved diffusion chain: all slabs for one 512-feature chunk
    // stay L2-resident through the whole dependency chain.
    for (int c = 0; c < FEAT / CHUNK; c++) {
        k_transpose<<<(N_NODES * (CHUNK / 4)) / 256, 256>>>(inputs, c);
        // xs[1] = S1 @ x0
        k_spmm<<<N_NODES, 128>>>(0, 0, -1, 1, c, 0);
        // xs[2] = 2*S1@xs[1] - x0      (write-once until GEMM -> stream)
        k_spmm<<<N_NODES, 128>>>(0, 1, 0, 2, c, 1);
        // xs[3] = S2 @ xs[1]           (x0 deliberately not reset)
        k_spmm<<<N_NODES, 128>>>(1, 1, -1, 3, c, 0);
        // xs[4] = 2*S2@xs[3] - xs[1]   (write-once until GEMM -> stream)
        k_spmm<<<N_NODES, 128>>>(1, 3, 1, 4, c, 1);
    }

    k_gemm<<<(BATCH * N_NODES) / 256, 256, WROWS * OUTD * sizeof(float)>>>(
        weights, biases, out);
}

// round 5
// speedup vs baseline: 1.3951x; 1.3951x over previous
#include <cuda_runtime.h>
#include <cuda_fp16.h>

// ---------------- problem constants ----------------
#define N_NODES 16384
#define N_EDGES 524288
#define BATCH   32
#define DIM     64
#define OUTD    64
#define FEAT    (BATCH * DIM)   /* 2048 */
#define NMAT    5
#define WROWS   (DIM * NMAT)    /* 320 */
#define FCHUNK  1024            /* feature chunk (halves) per SpMM launch */

// ---------------- device scratch (static: no allocations allowed) ----------
__device__ __align__(16) __half g_x[NMAT][(size_t)N_NODES * FEAT];  // ~335 MB
__device__ float g_inv_drow[N_NODES];
__device__ float g_inv_dcol[N_NODES];
__device__ int   g_cnt1[N_NODES];
__device__ int   g_cnt2[N_NODES];
__device__ int   g_rowptr1[N_NODES + 1];
__device__ int   g_rowptr2[N_NODES + 1];
__device__ int   g_pos1[N_NODES];
__device__ int   g_pos2[N_NODES];
__device__ int   g_adj_col[2][N_EDGES];
__device__ float g_adj_val[2][N_EDGES];

// ---------------- f32x2 packed-FMA helpers (sm_10x) ----------------
#define FMA_F32X2(d, a, b, c) \
    asm("fma.rn.f32x2 %0, %1, %2, %3;" \
        : "=l"(d) : "l"(a), "l"(b), "l"(c))
#define PACK_DUP_F32X2(out, x) \
    asm("mov.b64 %0, {%1, %1};" : "=l"(out) : "f"(x))
#define PACK_F32X2(out, lo, hi) \
    asm("mov.b64 %0, {%1, %2};" : "=l"(out) : "f"(lo), "f"(hi))

// ---------------- build kernels ----------------
__global__ void k_init() {
    int i = blockIdx.x * blockDim.x + threadIdx.x;
    if (i < N_NODES) {
        g_inv_drow[i] = 0.f;
        g_inv_dcol[i] = 0.f;
        g_cnt1[i] = 0;
        g_cnt2[i] = 0;
    }
}

__global__ void k_degree(const float* __restrict__ adj,
                         const int* __restrict__ rows,
                         const int* __restrict__ cols) {
    int e = blockIdx.x * blockDim.x + threadIdx.x;
    if (e < N_EDGES) {
        int r = rows[e], c = cols[e];
        float a = adj[e];
        atomicAdd(&g_inv_drow[r], a);
        atomicAdd(&g_inv_dcol[c], a);
        atomicAdd(&g_cnt1[c], 1);   // support1 CSR keyed by dst = cols
        atomicAdd(&g_cnt2[r], 1);   // support2 CSR keyed by dst = rows
    }
}

// single-block: invert degrees + exclusive scan both histograms
__global__ void k_scan() {
    __shared__ int sh[1024];
    int t = threadIdx.x;

    for (int i = t; i < N_NODES; i += 1024) {
        float d = g_inv_drow[i]; g_inv_drow[i] = (d > 0.f) ? (1.f / d) : 0.f;
        float c = g_inv_dcol[i]; g_inv_dcol[i] = (c > 0.f) ? (1.f / c) : 0.f;
    }
    __syncthreads();

    {
        int base = t * 16;
        int local[16];
        int s = 0;
        #pragma unroll
        for (int i = 0; i < 16; i++) { local[i] = s; s += g_cnt1[base + i]; }
        sh[t] = s;
        __syncthreads();
        for (int off = 1; off < 1024; off <<= 1) {
            int v = (t >= off) ? sh[t - off] : 0;
            __syncthreads();
            sh[t] += v;
            __syncthreads();
        }
        int prev = t ? sh[t - 1] : 0;
        #pragma unroll
        for (int i = 0; i < 16; i++) {
            int p = prev + local[i];
            g_rowptr1[base + i] = p;
            g_pos1[base + i] = p;
        }
        if (t == 1023) g_rowptr1[N_NODES] = sh[1023];
        __syncthreads();
    }
    {
        int base = t * 16;
        int local[16];
        int s = 0;
        #pragma unroll
        for (int i = 0; i < 16; i++) { local[i] = s; s += g_cnt2[base + i]; }
        sh[t] = s;
        __syncthreads();
        for (int off = 1; off < 1024; off <<= 1) {
            int v = (t >= off) ? sh[t - off] : 0;
            __syncthreads();
            sh[t] += v;
            __syncthreads();
        }
        int prev = t ? sh[t - 1] : 0;
        #pragma unroll
        for (int i = 0; i < 16; i++) {
            int p = prev + local[i];
            g_rowptr2[base + i] = p;
            g_pos2[base + i] = p;
        }
        if (t == 1023) g_rowptr2[N_NODES] = sh[1023];
    }
}

__global__ void k_fill(const float* __restrict__ adj,
                       const int* __restrict__ rows,
                       const int* __restrict__ cols) {
    int e = blockIdx.x * blockDim.x + threadIdx.x;
    if (e < N_EDGES) {
        int r = rows[e], c = cols[e];
        float a = adj[e];
        int s1 = atomicAdd(&g_pos1[c], 1);
        g_adj_col[0][s1] = r;
        g_adj_val[0][s1] = a * g_inv_drow[r];
        int s2 = atomicAdd(&g_pos2[r], 1);
        g_adj_col[1][s2] = c;
        g_adj_val[1][s2] = a * g_inv_dcol[c];
    }
}

// transpose + fp32->fp16: x0[n, b*64+d] = inputs[b, n, d]
// each thread: 8 consecutive d's -> one uint4 (8 halves) store
__global__ void k_transpose(const float* __restrict__ in) {
    int idx = blockIdx.x * blockDim.x + threadIdx.x;   // over N*FEAT/8
    int f8 = idx & 255;
    int n  = idx >> 8;
    int f  = f8 << 3;
    int b  = f >> 6;
    int d  = f & 63;
    const float4* src = reinterpret_cast<const float4*>(
        in + ((size_t)b * N_NODES * DIM + (size_t)n * DIM + d));
    float4 v0 = src[0];
    float4 v1 = src[1];
    __half2 h[4];
    h[0] = __floats2half2_rn(v0.x, v0.y);
    h[1] = __floats2half2_rn(v0.z, v0.w);
    h[2] = __floats2half2_rn(v1.x, v1.y);
    h[3] = __floats2half2_rn(v1.z, v1.w);
    *reinterpret_cast<uint4*>(&g_x[0][(size_t)n * FEAT + f]) =
        *reinterpret_cast<uint4*>(h);
}

// ---------------- SpMM (CSR gather, fp16 storage / fp32 accumulate) -------
// out = (S @ xin)            if m_z < 0
// out = 2*(S @ xin) - xz     otherwise
__global__ void __launch_bounds__(128)
k_spmm(int support, int m_in, int m_z, int m_out, int chunk, int streamout) {
    const int* __restrict__ rowptr = support ? g_rowptr2 : g_rowptr1;
    const int* __restrict__ colidx = g_adj_col[support];
    const float* __restrict__ val  = g_adj_val[support];
    const __half* __restrict__ xin = g_x[m_in];
    __half* __restrict__ xout      = g_x[m_out];

    int n = blockIdx.x;
    int fbase = chunk * FCHUNK + (threadIdx.x << 3);   // 8 halves per thread

    int e   = rowptr[n];
    int end = rowptr[n + 1];

    float acc[8];
    #pragma unroll
    for (int i = 0; i < 8; i++) acc[i] = 0.f;

    for (; e + 4 <= end; e += 4) {
        int   c0 = colidx[e],     c1 = colidx[e + 1];
        int   c2 = colidx[e + 2], c3 = colidx[e + 3];
        float v0 = val[e],     v1 = val[e + 1];
        float v2 = val[e + 2], v3 = val[e + 3];
        uint4 r0 = *reinterpret_cast<const uint4*>(xin + (size_t)c0 * FEAT + fbase);
        uint4 r1 = *reinterpret_cast<const uint4*>(xin + (size_t)c1 * FEAT + fbase);
        uint4 r2 = *reinterpret_cast<const uint4*>(xin + (size_t)c2 * FEAT + fbase);
        uint4 r3 = *reinterpret_cast<const uint4*>(xin + (size_t)c3 * FEAT + fbase);
        const __half2* h0 = reinterpret_cast<const __half2*>(&r0);
        const __half2* h1 = reinterpret_cast<const __half2*>(&r1);
        const __half2* h2 = reinterpret_cast<const __half2*>(&r2);
        const __half2* h3 = reinterpret_cast<const __half2*>(&r3);
        #pragma unroll
        for (int i = 0; i < 4; i++) {
            float2 f0 = __half22float2(h0[i]);
            float2 f1 = __half22float2(h1[i]);
            float2 f2 = __half22float2(h2[i]);
            float2 f3 = __half22float2(h3[i]);
            acc[2 * i]     += v0 * f0.x + v1 * f1.x + v2 * f2.x + v3 * f3.x;
            acc[2 * i + 1] += v0 * f0.y + v1 * f1.y + v2 * f2.y + v3 * f3.y;
        }
    }
    for (; e < end; e++) {
        int   c0 = colidx[e];
        float v0 = val[e];
        uint4 r0 = *reinterpret_cast<const uint4*>(xin + (size_t)c0 * FEAT + fbase);
        const __half2* h0 = reinterpret_cast<const __half2*>(&r0);
        #pragma unroll
        for (int i = 0; i < 4; i++) {
            float2 f0 = __half22float2(h0[i]);
            acc[2 * i]     += v0 * f0.x;
            acc[2 * i + 1] += v0 * f0.y;
        }
    }

    size_t ooff = (size_t)n * FEAT + fbase;
    if (m_z >= 0) {
        uint4 rz = __ldcs(reinterpret_cast<const uint4*>(g_x[m_z] + ooff));
        const __half2* hz = reinterpret_cast<const __half2*>(&rz);
        #pragma unroll
        for (int i = 0; i < 4; i++) {
            float2 fz = __half22float2(hz[i]);
            acc[2 * i]     = 2.f * acc[2 * i]     - fz.x;
            acc[2 * i + 1] = 2.f * acc[2 * i + 1] - fz.y;
        }
    }

    __half2 hout[4];
    #pragma unroll
    for (int i = 0; i < 4; i++)
        hout[i] = __floats2half2_rn(acc[2 * i], acc[2 * i + 1]);
    if (streamout)
        __stcs(reinterpret_cast<uint4*>(xout + ooff),
               *reinterpret_cast<uint4*>(hout));
    else
        *reinterpret_cast<uint4*>(xout + ooff) = *reinterpret_cast<uint4*>(hout);
}

// ---------------- fused output GEMM (fp16 x reads, packed f32x2 FMA) ------
// out[b,n,:] = sum_{d,m} x_m[n, b*64+d] * W[d*5+m, :]
__global__ void __launch_bounds__(256, 2)
k_gemm(const float* __restrict__ W, const float* __restrict__ bias,
       float* __restrict__ out) {
    extern __shared__ float sw[];   // WROWS*OUTD floats (80 KB)
    __shared__ float sb[OUTD];

    for (int i = threadIdx.x; i < WROWS * OUTD; i += 256) sw[i] = W[i];
    if (threadIdx.x < OUTD) sb[threadIdx.x] = bias[threadIdx.x];
    __syncthreads();

    int row = blockIdx.x * 256 + threadIdx.x;  // row = b*N + n
    int b = row >> 14;        // / 16384
    int n = row & 16383;
    const int off = n * FEAT + b * DIM;

    unsigned long long acc[32];   // 32 packed f32x2 accumulators = 64 outputs
    #pragma unroll
    for (int k = 0; k < 32; k++) PACK_F32X2(acc[k], sb[2 * k], sb[2 * k + 1]);

    #pragma unroll 1
    for (int d8 = 0; d8 < 8; ++d8) {
        float xf[NMAT][8];
        #pragma unroll
        for (int m = 0; m < NMAT; m++) {
            uint4 r = *reinterpret_cast<const uint4*>(
                &g_x[m][(size_t)off + d8 * 8]);
            const __half2* h = reinterpret_cast<const __half2*>(&r);
            #pragma unroll
            for (int i = 0; i < 4; i++) {
                float2 f = __half22float2(h[i]);
                xf[m][2 * i]     = f.x;
                xf[m][2 * i + 1] = f.y;
            }
        }
        #pragma unroll
        for (int j = 0; j < 8; j++) {
            int d = d8 * 8 + j;
            #pragma unroll
            for (int m = 0; m < NMAT; m++) {
                unsigned long long xx;
                PACK_DUP_F32X2(xx, xf[m][j]);
                const ulonglong2* wrow =
                    reinterpret_cast<const ulonglong2*>(sw + (d * NMAT + m) * OUTD);
                #pragma unroll
                for (int o4 = 0; o4 < 16; o4++) {
                    ulonglong2 w = wrow[o4];   // 4 W floats (broadcast LDS.128)
                    FMA_F32X2(acc[2 * o4],     w.x, xx, acc[2 * o4]);
                    FMA_F32X2(acc[2 * o4 + 1], w.y, xx, acc[2 * o4 + 1]);
                }
            }
        }
    }

    ulonglong2* op = reinterpret_cast<ulonglong2*>(out + (size_t)row * OUTD);
    #pragma unroll
    for (int o4 = 0; o4 < 16; o4++)
        op[o4] = make_ulonglong2(acc[2 * o4], acc[2 * o4 + 1]);
}

// ---------------- launch ----------------
extern "C" void kernel_launch(void* const* d_in, const int* in_sizes, int n_in,
                              void* d_out, int out_size) {
    const float* inputs  = (const float*)d_in[0];
    const float* adj     = (const float*)d_in[1];
    const int*   rows    = (const int*)d_in[2];
    const int*   cols    = (const int*)d_in[3];
    const float* weights = (const float*)d_in[4];
    const float* biases  = (const float*)d_in[5];
    float*       out     = (float*)d_out;

    cudaFuncSetAttribute(k_gemm, cudaFuncAttributeMaxDynamicSharedMemorySize,
                         WROWS * OUTD * (int)sizeof(float));

    k_init<<<(N_NODES + 255) / 256, 256>>>();
    k_degree<<<N_EDGES / 256, 256>>>(adj, rows, cols);
    k_scan<<<1, 1024>>>();
    k_fill<<<N_EDGES / 256, 256>>>(adj, rows, cols);
    k_transpose<<<(N_NODES * (FEAT / 8)) / 256, 256>>>(inputs);

    // Chunk-interleaved diffusion chain; 1024-halves chunks (2 KB/node-row,
    // 32 MB/slab) so all live slabs stay L2-resident through the chain.
    for (int c = 0; c < FEAT / FCHUNK; c++) {
        // xs[1] = S1 @ x0
        k_spmm<<<N_NODES, 128>>>(0, 0, -1, 1, c, 0);
        // xs[2] = 2*S1@xs[1] - x0      (write-once until GEMM -> stream)
        k_spmm<<<N_NODES, 128>>>(0, 1, 0, 2, c, 1);
        // xs[3] = S2 @ xs[1]           (x0 deliberately not reset)
        k_spmm<<<N_NODES, 128>>>(1, 1, -1, 3, c, 0);
        // xs[4] = 2*S2@xs[3] - xs[1]   (write-once until GEMM -> stream)
        k_spmm<<<N_NODES, 128>>>(1, 3, 1, 4, c, 1);
    }

    k_gemm<<<(BATCH * N_NODES) / 256, 256, WROWS * OUTD * sizeof(float)>>>(
        weights, biases, out);
}